// round 7
// baseline (speedup 1.0000x reference)
#include <cuda_runtime.h>
#include <cuda_fp16.h>
#include <cstdint>
#include <cstddef>

#define KCODES 8192
#define DDIM   256
#define NROWS  32768
#define GAMMA_F 0.99f
#define EPS_F   1e-5f

#define NKC  8              // K-chunks of 32 (K=256, plain fp16)
#define LDH  40             // padded halves per smem row (80B)
#define MARGIN 0.15f

// ---------------- device scratch ----------------
__device__ __half g_Az[(size_t)NROWS * DDIM];
__device__ __half g_Bw[(size_t)KCODES * DDIM];
__device__ unsigned long long g_M[(size_t)NROWS * 64];   // per (row, coltile) best key
__device__ unsigned long long g_best[NROWS];
__device__ float g_wnorm[KCODES];
__device__ float g_cnt[KCODES];
__device__ float g_commit;
__device__ float g_nsum;

// ---------------- helpers ----------------
__device__ __forceinline__ uint32_t smem_u32(const void* p) {
    uint32_t a;
    asm("{ .reg .u64 t; cvta.to.shared.u64 t, %1; cvt.u32.u64 %0, t; }" : "=r"(a) : "l"(p));
    return a;
}
__device__ __forceinline__ void cp16(uint32_t s, const void* g) {
    asm volatile("cp.async.cg.shared.global [%0], [%1], 16;" :: "r"(s), "l"(g));
}
#define CP_COMMIT() asm volatile("cp.async.commit_group;" ::: "memory")
#define CP_WAIT(n)  asm volatile("cp.async.wait_group %0;" :: "n"(n) : "memory")

__device__ __forceinline__ void ldsm4(uint32_t* r, uint32_t addr) {
    asm volatile("ldmatrix.sync.aligned.m8n8.x4.shared.b16 {%0,%1,%2,%3}, [%4];"
                 : "=r"(r[0]), "=r"(r[1]), "=r"(r[2]), "=r"(r[3]) : "r"(addr));
}
__device__ __forceinline__ void mma16816(float* c, const uint32_t* a,
                                         uint32_t b0, uint32_t b1) {
    asm volatile(
        "mma.sync.aligned.m16n8k16.row.col.f32.f16.f16.f32 "
        "{%0,%1,%2,%3}, {%4,%5,%6,%7}, {%8,%9}, {%0,%1,%2,%3};"
        : "+f"(c[0]), "+f"(c[1]), "+f"(c[2]), "+f"(c[3])
        : "r"(a[0]), "r"(a[1]), "r"(a[2]), "r"(a[3]), "r"(b0), "r"(b1));
}
__device__ __forceinline__ unsigned long long fkey(float s, int code) {
    unsigned u = __float_as_uint(s);
    u = (u & 0x80000000u) ? ~u : (u | 0x80000000u);
    return ((unsigned long long)u << 32) | (unsigned)(KCODES - 1 - code);
}
__device__ __forceinline__ float key2score(unsigned long long k) {
    unsigned u = (unsigned)(k >> 32);
    u = (u & 0x80000000u) ? (u & 0x7fffffffu) : ~u;
    return __uint_as_float(u);
}
__device__ __forceinline__ unsigned long long umax64(unsigned long long a, unsigned long long b) {
    return a > b ? a : b;
}

// ---------------- prep: plain fp16 casts ----------------
__global__ void k_prep(const float* __restrict__ ze, const float* __restrict__ W) {
    int i = blockIdx.x * 256 + threadIdx.x;       // covers NROWS*DDIM
    g_Az[i] = __float2half_rn(ze[i]);
    if (i < KCODES * DDIM) g_Bw[i] = __float2half_rn(W[i]);
}

// ---------------- init ----------------
__global__ void k_init(const float* __restrict__ W, const float* __restrict__ mt,
                       float* __restrict__ out_mt) {
    int i = blockIdx.x * blockDim.x + threadIdx.x;   // exactly NROWS*64 = KCODES*DDIM
    out_mt[i] = GAMMA_F * mt[i];
    g_M[i] = 0ull;
    if (i < KCODES) {
        const float4* w = (const float4*)(W + (size_t)i * DDIM);
        float s = 0.f;
        #pragma unroll 8
        for (int q = 0; q < DDIM / 4; ++q) {
            float4 v = w[q];
            s += v.x * v.x + v.y * v.y + v.z * v.z + v.w * v.w;
        }
        g_wnorm[i] = 0.5f * s;
        g_cnt[i]   = 0.f;
    }
    if (i == 0) { g_commit = 0.f; g_nsum = 0.f; }
}

// ---------------- phase 1: fp16 HMMA approx score GEMM, per-tile max keys ----------------
__global__ void __launch_bounds__(256, 2) k_gemm1() {
    __shared__ __half sA[2][128 * LDH];
    __shared__ __half sB[2][128 * LDH];

    const int tid  = threadIdx.x;
    const int wid  = tid >> 5;
    const int lane = tid & 31;
    const int rowBase = blockIdx.x * 128;
    const int nTile   = blockIdx.y;
    const int nBase   = nTile * 128;

    const int lr = tid >> 2;
    const int lc = tid & 3;
    uint32_t aS[2], bS[2];
    #pragma unroll
    for (int b = 0; b < 2; ++b) {
        aS[b] = smem_u32(&sA[b][0]);
        bS[b] = smem_u32(&sB[b][0]);
    }

    float acc[2][8][4];
    #pragma unroll
    for (int i = 0; i < 2; ++i)
        #pragma unroll
        for (int j = 0; j < 8; ++j)
            #pragma unroll
            for (int q = 0; q < 4; ++q) acc[i][j][q] = 0.f;

    {
        #pragma unroll
        for (int p = 0; p < 2; ++p) {
            int r = lr + 64 * p;
            cp16(aS[0] + r * (LDH * 2) + lc * 16,
                 g_Az + (size_t)(rowBase + r) * DDIM + lc * 8);
            cp16(bS[0] + r * (LDH * 2) + lc * 16,
                 g_Bw + (size_t)(nBase + r) * DDIM + lc * 8);
        }
        CP_COMMIT();
    }

    const int mOff = (wid >> 1) * 32;
    const int nOff = (wid & 1) * 64;
    const int lmRow = lane & 15;
    const int lmCol = (lane >> 4) * 16;

    for (int kc = 0; kc < NKC; ++kc) {
        const int buf = kc & 1;
        if (kc + 1 < NKC) {
            const int nb = buf ^ 1;
            const int ko = (kc + 1) * 32;
            #pragma unroll
            for (int p = 0; p < 2; ++p) {
                int r = lr + 64 * p;
                cp16(aS[nb] + r * (LDH * 2) + lc * 16,
                     g_Az + (size_t)(rowBase + r) * DDIM + ko + lc * 8);
                cp16(bS[nb] + r * (LDH * 2) + lc * 16,
                     g_Bw + (size_t)(nBase + r) * DDIM + ko + lc * 8);
            }
            CP_COMMIT();
            CP_WAIT(1);
        } else {
            CP_WAIT(0);
        }
        __syncthreads();

        #pragma unroll
        for (int k16 = 0; k16 < 2; ++k16) {
            const int kb = k16 * 32 + lmCol;
            uint32_t af[2][4];
            #pragma unroll
            for (int i = 0; i < 2; ++i)
                ldsm4(af[i], aS[buf] + (mOff + i * 16 + lmRow) * (LDH * 2) + kb);
            uint32_t bf[4][4];
            #pragma unroll
            for (int g = 0; g < 4; ++g)
                ldsm4(bf[g], bS[buf] + (nOff + g * 16 + lmRow) * (LDH * 2) + kb);
            #pragma unroll
            for (int i = 0; i < 2; ++i)
                #pragma unroll
                for (int j = 0; j < 8; ++j) {
                    const int g = j >> 1, h = j & 1;
                    mma16816(acc[i][j], af[i], bf[g][h], bf[g][h + 2]);
                }
        }
        __syncthreads();
    }

    // epilogue: per-row tile-best key -> g_M[row][nTile]
    #pragma unroll
    for (int i = 0; i < 2; ++i)
        #pragma unroll
        for (int h = 0; h < 2; ++h) {
            const int row = rowBase + mOff + i * 16 + (lane >> 2) + h * 8;
            unsigned long long key = 0ull;
            #pragma unroll
            for (int j = 0; j < 8; ++j) {
                const int col = nBase + nOff + j * 8 + (lane & 3) * 2;
                float s0 = acc[i][j][h * 2]     - __ldg(&g_wnorm[col]);
                float s1 = acc[i][j][h * 2 + 1] - __ldg(&g_wnorm[col + 1]);
                key = umax64(key, fkey(s0, col));
                key = umax64(key, fkey(s1, col + 1));
            }
            key = umax64(key, __shfl_xor_sync(0xffffffffu, key, 1));
            key = umax64(key, __shfl_xor_sync(0xffffffffu, key, 2));
            if ((lane & 3) == 0) atomicMax(&g_M[(size_t)row * 64 + nTile], key);
        }
}

// ---------------- phase 2: exact fp32 rescore of near-max tiles ----------------
// one warp per row; 8 warps per CTA
__global__ void __launch_bounds__(256, 4) k_phase2(const float* __restrict__ ze,
                                                   const float* __restrict__ W) {
    __shared__ float zs[8][DDIM];
    const int wid  = threadIdx.x >> 5;
    const int lane = threadIdx.x & 31;
    const int row  = blockIdx.x * 8 + wid;

    // load z row into smem
    {
        const float4* zg = (const float4*)(ze + (size_t)row * DDIM);
        ((float4*)zs[wid])[lane]      = zg[lane];
        ((float4*)zs[wid])[lane + 32] = zg[lane + 32];
    }
    __syncwarp();

    unsigned long long k0 = g_M[(size_t)row * 64 + lane];
    unsigned long long k1 = g_M[(size_t)row * 64 + 32 + lane];
    unsigned long long m = umax64(k0, k1);
    #pragma unroll
    for (int off = 16; off > 0; off >>= 1)
        m = umax64(m, __shfl_xor_sync(0xffffffffu, m, off));
    const float thr = key2score(m) - MARGIN;

    unsigned long long best = 0ull;
    for (int t = 0; t < 64; ++t) {
        unsigned long long kt = __shfl_sync(0xffffffffu, (t < 32) ? k0 : k1, t & 31);
        if (key2score(kt) >= thr) {
            const int code0 = t * 128 + lane * 4;
            float a0 = 0.f, a1 = 0.f, a2 = 0.f, a3 = 0.f;
            const float* w0 = W + (size_t)code0 * DDIM;
            #pragma unroll 4
            for (int d = 0; d < DDIM; d += 4) {
                float4 z4 = *(const float4*)&zs[wid][d];
                float4 wv0 = *(const float4*)(w0 + d);
                float4 wv1 = *(const float4*)(w0 + DDIM + d);
                float4 wv2 = *(const float4*)(w0 + 2 * DDIM + d);
                float4 wv3 = *(const float4*)(w0 + 3 * DDIM + d);
                a0 = fmaf(z4.x, wv0.x, fmaf(z4.y, wv0.y, fmaf(z4.z, wv0.z, fmaf(z4.w, wv0.w, a0))));
                a1 = fmaf(z4.x, wv1.x, fmaf(z4.y, wv1.y, fmaf(z4.z, wv1.z, fmaf(z4.w, wv1.w, a1))));
                a2 = fmaf(z4.x, wv2.x, fmaf(z4.y, wv2.y, fmaf(z4.z, wv2.z, fmaf(z4.w, wv2.w, a2))));
                a3 = fmaf(z4.x, wv3.x, fmaf(z4.y, wv3.y, fmaf(z4.z, wv3.z, fmaf(z4.w, wv3.w, a3))));
            }
            best = umax64(best, fkey(a0 - __ldg(&g_wnorm[code0]),     code0));
            best = umax64(best, fkey(a1 - __ldg(&g_wnorm[code0 + 1]), code0 + 1));
            best = umax64(best, fkey(a2 - __ldg(&g_wnorm[code0 + 2]), code0 + 2));
            best = umax64(best, fkey(a3 - __ldg(&g_wnorm[code0 + 3]), code0 + 3));
        }
    }
    #pragma unroll
    for (int off = 16; off > 0; off >>= 1)
        best = umax64(best, __shfl_xor_sync(0xffffffffu, best, off));
    if (lane == 0) g_best[row] = best;
}

// ---------------- gather/scatter ----------------
__global__ void k_scatter(const float* __restrict__ ze, const float* __restrict__ W,
                          float* __restrict__ out_zq, float* __restrict__ out_idx,
                          float* __restrict__ out_mt) {
    const int tid  = threadIdx.x;
    const int row  = blockIdx.x * 4 + (tid >> 6);
    const int lane = tid & 63;
    const int idx  = KCODES - 1 - (int)(g_best[row] & 0xffffffffu);

    const float4 z = *(const float4*)(ze + (size_t)row * DDIM + lane * 4);
    const float4 w = *(const float4*)(W  + (size_t)idx * DDIM + lane * 4);

    float4 q;
    q.x = z.x + (w.x - z.x);
    q.y = z.y + (w.y - z.y);
    q.z = z.z + (w.z - z.z);
    q.w = z.w + (w.w - z.w);
    *(float4*)(out_zq + (size_t)row * DDIM + lane * 4) = q;

    float dx = w.x - z.x, dy = w.y - z.y, dz = w.z - z.z, dw = w.w - z.w;
    float csum = dx * dx + dy * dy + dz * dz + dw * dw;

    const float s = 1.0f - GAMMA_F;
    float* mptr = out_mt + (size_t)idx * DDIM + lane * 4;
    atomicAdd(mptr + 0, s * z.x);
    atomicAdd(mptr + 1, s * z.y);
    atomicAdd(mptr + 2, s * z.z);
    atomicAdd(mptr + 3, s * z.w);

    if (lane == 0) {
        atomicAdd(&g_cnt[idx], 1.0f);
        out_idx[row] = (float)idx;
    }

    __shared__ float red[8];
    #pragma unroll
    for (int off = 16; off > 0; off >>= 1)
        csum += __shfl_down_sync(0xffffffffu, csum, off);
    if ((tid & 31) == 0) red[tid >> 5] = csum;
    __syncthreads();
    if (tid < 8) {
        float v = red[tid];
        #pragma unroll
        for (int off = 4; off > 0; off >>= 1)
            v += __shfl_down_sync(0xffu, v, off);
        if (tid == 0) atomicAdd(&g_commit, v);
    }
}

// ---------------- Nt_new + n ----------------
__global__ void k_fin_nt(const float* __restrict__ Nt, float* __restrict__ out_Nt) {
    int k = blockIdx.x * 256 + threadIdx.x;
    float v = GAMMA_F * Nt[k] + (1.0f - GAMMA_F) * g_cnt[k];
    out_Nt[k] = v;
    __shared__ float red[8];
    float s = v;
    #pragma unroll
    for (int off = 16; off > 0; off >>= 1)
        s += __shfl_down_sync(0xffffffffu, s, off);
    if ((threadIdx.x & 31) == 0) red[threadIdx.x >> 5] = s;
    __syncthreads();
    if (threadIdx.x < 8) {
        float t = red[threadIdx.x];
        #pragma unroll
        for (int off = 4; off > 0; off >>= 1)
            t += __shfl_down_sync(0xffu, t, off);
        if (threadIdx.x == 0) atomicAdd(&g_nsum, t);
    }
}

// ---------------- embedW_new + commit ----------------
__global__ void k_fin_w(const float* __restrict__ out_Nt,
                        const float* __restrict__ out_mt,
                        float* __restrict__ out_W,
                        float* __restrict__ out_commit) {
    int i = blockIdx.x * 256 + threadIdx.x;
    int k = i >> 8;
    float n  = g_nsum;
    float Nn = (out_Nt[k] + EPS_F) * n / (n + (float)KCODES * EPS_F);
    out_W[i] = out_mt[i] / Nn;
    if (i == 0) *out_commit = g_commit / (float)((size_t)NROWS * DDIM);
}

// ---------------- launch ----------------
extern "C" void kernel_launch(void* const* d_in, const int* in_sizes, int n_in,
                              void* d_out, int out_size) {
    const float* ze = (const float*)d_in[0];
    const float* W  = (const float*)d_in[1];
    const float* mt = (const float*)d_in[2];
    const float* Nt = (const float*)d_in[3];
    float* out = (float*)d_out;

    const size_t off_zq     = 0;
    const size_t off_commit = (size_t)NROWS * DDIM;
    const size_t off_idx    = off_commit + 1;
    const size_t off_W      = off_idx + NROWS;
    const size_t off_mt     = off_W + (size_t)KCODES * DDIM;
    const size_t off_Nt     = off_mt + (size_t)KCODES * DDIM;

    k_prep<<<(NROWS * DDIM) / 256, 256>>>(ze, W);
    k_init<<<(KCODES * DDIM) / 256, 256>>>(W, mt, out + off_mt);

    dim3 grid(NROWS / 128, KCODES / 128);   // x = rowtile (fast) -> B coltile L2-hot
    k_gemm1<<<grid, 256>>>();

    k_phase2<<<NROWS / 8, 256>>>(ze, W);
    k_scatter<<<NROWS / 4, 256>>>(ze, W, out + off_zq, out + off_idx, out + off_mt);
    k_fin_nt<<<KCODES / 256, 256>>>(Nt, out + off_Nt);
    k_fin_w<<<(KCODES * DDIM) / 256, 256>>>(out + off_Nt, out + off_mt,
                                            out + off_W, out + off_commit);
}

// round 8
// speedup vs baseline: 2.2004x; 2.2004x over previous
#include <cuda_runtime.h>
#include <cuda_fp16.h>
#include <cstdint>
#include <cstddef>

#define KCODES 8192
#define DDIM   256
#define NROWS  32768
#define GAMMA_F 0.99f
#define EPS_F   1e-5f

#define NKC  8              // K-chunks of 32 (K=256)
#define NS   4              // cp.async pipeline stages
#define LDH  40             // padded halves per smem row (80B)
#define MARGIN 0.1f
#define NGRP (KCODES / 16)  // 512 16-code groups

// ---------------- device scratch ----------------
__device__ __half g_Az[(size_t)NROWS * DDIM];
__device__ __half g_Bw[(size_t)KCODES * DDIM];
__device__ unsigned long long g_M2[(size_t)NROWS * NGRP];  // per (row,16-code group) best key
__device__ unsigned long long g_best[NROWS];
__device__ float g_wnorm[KCODES];
__device__ float g_cnt[KCODES];
__device__ float g_commit;
__device__ float g_nsum;

// ---------------- helpers ----------------
__device__ __forceinline__ uint32_t smem_u32(const void* p) {
    uint32_t a;
    asm("{ .reg .u64 t; cvta.to.shared.u64 t, %1; cvt.u32.u64 %0, t; }" : "=r"(a) : "l"(p));
    return a;
}
__device__ __forceinline__ void cp16(uint32_t s, const void* g) {
    asm volatile("cp.async.cg.shared.global [%0], [%1], 16;" :: "r"(s), "l"(g));
}
#define CP_COMMIT() asm volatile("cp.async.commit_group;" ::: "memory")
#define CP_WAIT(n)  asm volatile("cp.async.wait_group %0;" :: "n"(n) : "memory")

__device__ __forceinline__ void ldsm4(uint32_t* r, uint32_t addr) {
    asm volatile("ldmatrix.sync.aligned.m8n8.x4.shared.b16 {%0,%1,%2,%3}, [%4];"
                 : "=r"(r[0]), "=r"(r[1]), "=r"(r[2]), "=r"(r[3]) : "r"(addr));
}
__device__ __forceinline__ void mma16816(float* c, const uint32_t* a,
                                         uint32_t b0, uint32_t b1) {
    asm volatile(
        "mma.sync.aligned.m16n8k16.row.col.f32.f16.f16.f32 "
        "{%0,%1,%2,%3}, {%4,%5,%6,%7}, {%8,%9}, {%0,%1,%2,%3};"
        : "+f"(c[0]), "+f"(c[1]), "+f"(c[2]), "+f"(c[3])
        : "r"(a[0]), "r"(a[1]), "r"(a[2]), "r"(a[3]), "r"(b0), "r"(b1));
}
__device__ __forceinline__ unsigned long long fkey(float s, int code) {
    unsigned u = __float_as_uint(s);
    u = (u & 0x80000000u) ? ~u : (u | 0x80000000u);
    return ((unsigned long long)u << 32) | (unsigned)(KCODES - 1 - code);
}
__device__ __forceinline__ float key2score(unsigned long long k) {
    unsigned u = (unsigned)(k >> 32);
    u = (u & 0x80000000u) ? (u & 0x7fffffffu) : ~u;
    return __uint_as_float(u);
}
__device__ __forceinline__ unsigned long long umax64(unsigned long long a, unsigned long long b) {
    return a > b ? a : b;
}

// ---------------- prep: plain fp16 casts ----------------
__global__ void k_prep(const float* __restrict__ ze, const float* __restrict__ W) {
    int i = blockIdx.x * 256 + threadIdx.x;       // covers NROWS*DDIM
    g_Az[i] = __float2half_rn(ze[i]);
    if (i < KCODES * DDIM) g_Bw[i] = __float2half_rn(W[i]);
}

// ---------------- init ----------------
__global__ void k_init(const float* __restrict__ W, const float* __restrict__ mt,
                       float* __restrict__ out_mt) {
    int i = blockIdx.x * blockDim.x + threadIdx.x;
    out_mt[i] = GAMMA_F * mt[i];
    if (i < KCODES) {
        const float4* w = (const float4*)(W + (size_t)i * DDIM);
        float s = 0.f;
        #pragma unroll 8
        for (int q = 0; q < DDIM / 4; ++q) {
            float4 v = w[q];
            s += v.x * v.x + v.y * v.y + v.z * v.z + v.w * v.w;
        }
        g_wnorm[i] = 0.5f * s;
        g_cnt[i]   = 0.f;
    }
    if (i == 0) { g_commit = 0.f; g_nsum = 0.f; }
}

// ---------------- phase 1: fp16 HMMA approx GEMM, per-16-code-group max keys ----------------
__global__ void __launch_bounds__(256, 2) k_gemm1() {
    __shared__ __half sA[NS][128 * LDH];
    __shared__ __half sB[NS][128 * LDH];

    const int tid  = threadIdx.x;
    const int wid  = tid >> 5;
    const int lane = tid & 31;
    const int rowBase = blockIdx.x * 128;
    const int nTile   = blockIdx.y;
    const int nBase   = nTile * 128;

    const int lr = tid >> 2;
    const int lc = tid & 3;
    uint32_t aS[NS], bS[NS];
    #pragma unroll
    for (int s = 0; s < NS; ++s) {
        aS[s] = smem_u32(&sA[s][0]);
        bS[s] = smem_u32(&sB[s][0]);
    }

    float acc[2][8][4];
    #pragma unroll
    for (int i = 0; i < 2; ++i)
        #pragma unroll
        for (int j = 0; j < 8; ++j)
            #pragma unroll
            for (int q = 0; q < 4; ++q) acc[i][j][q] = 0.f;

    // prologue: stages 0..NS-2
    #pragma unroll
    for (int s = 0; s < NS - 1; ++s) {
        const int ko = s * 32;
        #pragma unroll
        for (int p = 0; p < 2; ++p) {
            int r = lr + 64 * p;
            cp16(aS[s] + r * (LDH * 2) + lc * 16,
                 g_Az + (size_t)(rowBase + r) * DDIM + ko + lc * 8);
            cp16(bS[s] + r * (LDH * 2) + lc * 16,
                 g_Bw + (size_t)(nBase + r) * DDIM + ko + lc * 8);
        }
        CP_COMMIT();
    }

    const int mOff = (wid >> 1) * 32;
    const int nOff = (wid & 1) * 64;
    const int lmRow = lane & 15;
    const int lmCol = (lane >> 4) * 16;

    for (int kc = 0; kc < NKC; ++kc) {
        CP_WAIT(NS - 2);
        __syncthreads();
        // issue chunk kc+NS-1 into stage (kc+NS-1)%NS (== (kc-1)%NS, safe post-sync)
        {
            const int nc = kc + NS - 1;
            if (nc < NKC) {
                const int st = nc & (NS - 1);
                const int ko = nc * 32;
                #pragma unroll
                for (int p = 0; p < 2; ++p) {
                    int r = lr + 64 * p;
                    cp16(aS[st] + r * (LDH * 2) + lc * 16,
                         g_Az + (size_t)(rowBase + r) * DDIM + ko + lc * 8);
                    cp16(bS[st] + r * (LDH * 2) + lc * 16,
                         g_Bw + (size_t)(nBase + r) * DDIM + ko + lc * 8);
                }
            }
            CP_COMMIT();   // always commit (possibly empty) to keep group count aligned
        }

        const int buf = kc & (NS - 1);
        #pragma unroll
        for (int k16 = 0; k16 < 2; ++k16) {
            const int kb = k16 * 32 + lmCol;
            uint32_t af[2][4];
            #pragma unroll
            for (int i = 0; i < 2; ++i)
                ldsm4(af[i], aS[buf] + (mOff + i * 16 + lmRow) * (LDH * 2) + kb);
            uint32_t bf[4][4];
            #pragma unroll
            for (int g = 0; g < 4; ++g)
                ldsm4(bf[g], bS[buf] + (nOff + g * 16 + lmRow) * (LDH * 2) + kb);
            #pragma unroll
            for (int i = 0; i < 2; ++i)
                #pragma unroll
                for (int j = 0; j < 8; ++j) {
                    const int g = j >> 1, h = j & 1;
                    mma16816(acc[i][j], af[i], bf[g][h], bf[g][h + 2]);
                }
        }
    }

    // epilogue: per-row per-16-code-group best key (unique writer -> plain store)
    const int gBase = (nBase >> 4) + (nOff >> 4);
    #pragma unroll
    for (int i = 0; i < 2; ++i)
        #pragma unroll
        for (int h = 0; h < 2; ++h) {
            const int row = rowBase + mOff + i * 16 + (lane >> 2) + h * 8;
            #pragma unroll
            for (int t = 0; t < 4; ++t) {
                unsigned long long key = 0ull;
                #pragma unroll
                for (int jj = 0; jj < 2; ++jj) {
                    const int j = 2 * t + jj;
                    const int col = nBase + nOff + j * 8 + (lane & 3) * 2;
                    float s0 = acc[i][j][h * 2]     - __ldg(&g_wnorm[col]);
                    float s1 = acc[i][j][h * 2 + 1] - __ldg(&g_wnorm[col + 1]);
                    key = umax64(key, fkey(s0, col));
                    key = umax64(key, fkey(s1, col + 1));
                }
                key = umax64(key, __shfl_xor_sync(0xffffffffu, key, 1));
                key = umax64(key, __shfl_xor_sync(0xffffffffu, key, 2));
                if ((lane & 3) == 0)
                    g_M2[(size_t)row * NGRP + gBase + t] = key;
            }
        }
}

// ---------------- phase 2: exact fp32 rescore of near-max 16-code groups ----------------
__global__ void __launch_bounds__(256, 4) k_phase2(const float* __restrict__ ze,
                                                   const float* __restrict__ W) {
    __shared__ float zs[8][DDIM];
    const int wid  = threadIdx.x >> 5;
    const int lane = threadIdx.x & 31;
    const int row  = blockIdx.x * 8 + wid;

    {
        const float4* zg = (const float4*)(ze + (size_t)row * DDIM);
        ((float4*)zs[wid])[lane]      = zg[lane];
        ((float4*)zs[wid])[lane + 32] = zg[lane + 32];
    }
    __syncwarp();

    const unsigned long long* Mrow = g_M2 + (size_t)row * NGRP;
    unsigned long long m = 0ull;
    #pragma unroll
    for (int i = 0; i < 16; ++i) m = umax64(m, Mrow[i * 32 + lane]);
    #pragma unroll
    for (int off = 16; off > 0; off >>= 1)
        m = umax64(m, __shfl_xor_sync(0xffffffffu, m, off));
    const float thr = key2score(m) - MARGIN;

    unsigned long long best = 0ull;
    const float* zh = zs[wid] + (lane & 1) * 128;
    for (int i = 0; i < 16; ++i) {
        unsigned long long kk = Mrow[i * 32 + lane];
        unsigned mask = __ballot_sync(0xffffffffu, key2score(kk) >= thr);
        while (mask) {
            const int b = __ffs(mask) - 1;
            mask &= mask - 1;
            const int g = i * 32 + b;
            const int code = g * 16 + (lane >> 1);
            const float* wp = W + (size_t)code * DDIM + (lane & 1) * 128;
            float a0 = 0.f, a1 = 0.f, a2 = 0.f, a3 = 0.f;
            #pragma unroll 8
            for (int d = 0; d < 128; d += 16) {
                float4 z0 = *(const float4*)(zh + d);
                float4 z1 = *(const float4*)(zh + d + 4);
                float4 z2 = *(const float4*)(zh + d + 8);
                float4 z3 = *(const float4*)(zh + d + 12);
                float4 w0 = *(const float4*)(wp + d);
                float4 w1 = *(const float4*)(wp + d + 4);
                float4 w2 = *(const float4*)(wp + d + 8);
                float4 w3 = *(const float4*)(wp + d + 12);
                a0 = fmaf(z0.x, w0.x, fmaf(z0.y, w0.y, fmaf(z0.z, w0.z, fmaf(z0.w, w0.w, a0))));
                a1 = fmaf(z1.x, w1.x, fmaf(z1.y, w1.y, fmaf(z1.z, w1.z, fmaf(z1.w, w1.w, a1))));
                a2 = fmaf(z2.x, w2.x, fmaf(z2.y, w2.y, fmaf(z2.z, w2.z, fmaf(z2.w, w2.w, a2))));
                a3 = fmaf(z3.x, w3.x, fmaf(z3.y, w3.y, fmaf(z3.z, w3.z, fmaf(z3.w, w3.w, a3))));
            }
            float acc = (a0 + a1) + (a2 + a3);
            acc += __shfl_xor_sync(0xffffffffu, acc, 1);
            if (!(lane & 1))
                best = umax64(best, fkey(acc - __ldg(&g_wnorm[code]), code));
        }
    }
    #pragma unroll
    for (int off = 16; off > 0; off >>= 1)
        best = umax64(best, __shfl_xor_sync(0xffffffffu, best, off));
    if (lane == 0) g_best[row] = best;
}

// ---------------- gather/scatter ----------------
__global__ void k_scatter(const float* __restrict__ ze, const float* __restrict__ W,
                          float* __restrict__ out_zq, float* __restrict__ out_idx,
                          float* __restrict__ out_mt) {
    const int tid  = threadIdx.x;
    const int row  = blockIdx.x * 4 + (tid >> 6);
    const int lane = tid & 63;
    const int idx  = KCODES - 1 - (int)(g_best[row] & 0xffffffffu);

    const float4 z = *(const float4*)(ze + (size_t)row * DDIM + lane * 4);
    const float4 w = *(const float4*)(W  + (size_t)idx * DDIM + lane * 4);

    float4 q;
    q.x = z.x + (w.x - z.x);
    q.y = z.y + (w.y - z.y);
    q.z = z.z + (w.z - z.z);
    q.w = z.w + (w.w - z.w);
    *(float4*)(out_zq + (size_t)row * DDIM + lane * 4) = q;

    float dx = w.x - z.x, dy = w.y - z.y, dz = w.z - z.z, dw = w.w - z.w;
    float csum = dx * dx + dy * dy + dz * dz + dw * dw;

    const float s = 1.0f - GAMMA_F;
    float* mptr = out_mt + (size_t)idx * DDIM + lane * 4;
    atomicAdd(mptr + 0, s * z.x);
    atomicAdd(mptr + 1, s * z.y);
    atomicAdd(mptr + 2, s * z.z);
    atomicAdd(mptr + 3, s * z.w);

    if (lane == 0) {
        atomicAdd(&g_cnt[idx], 1.0f);
        out_idx[row] = (float)idx;
    }

    __shared__ float red[8];
    #pragma unroll
    for (int off = 16; off > 0; off >>= 1)
        csum += __shfl_down_sync(0xffffffffu, csum, off);
    if ((tid & 31) == 0) red[tid >> 5] = csum;
    __syncthreads();
    if (tid < 8) {
        float v = red[tid];
        #pragma unroll
        for (int off = 4; off > 0; off >>= 1)
            v += __shfl_down_sync(0xffu, v, off);
        if (tid == 0) atomicAdd(&g_commit, v);
    }
}

// ---------------- Nt_new + n ----------------
__global__ void k_fin_nt(const float* __restrict__ Nt, float* __restrict__ out_Nt) {
    int k = blockIdx.x * 256 + threadIdx.x;
    float v = GAMMA_F * Nt[k] + (1.0f - GAMMA_F) * g_cnt[k];
    out_Nt[k] = v;
    __shared__ float red[8];
    float s = v;
    #pragma unroll
    for (int off = 16; off > 0; off >>= 1)
        s += __shfl_down_sync(0xffffffffu, s, off);
    if ((threadIdx.x & 31) == 0) red[threadIdx.x >> 5] = s;
    __syncthreads();
    if (threadIdx.x < 8) {
        float t = red[threadIdx.x];
        #pragma unroll
        for (int off = 4; off > 0; off >>= 1)
            t += __shfl_down_sync(0xffu, t, off);
        if (threadIdx.x == 0) atomicAdd(&g_nsum, t);
    }
}

// ---------------- embedW_new + commit ----------------
__global__ void k_fin_w(const float* __restrict__ out_Nt,
                        const float* __restrict__ out_mt,
                        float* __restrict__ out_W,
                        float* __restrict__ out_commit) {
    int i = blockIdx.x * 256 + threadIdx.x;
    int k = i >> 8;
    float n  = g_nsum;
    float Nn = (out_Nt[k] + EPS_F) * n / (n + (float)KCODES * EPS_F);
    out_W[i] = out_mt[i] / Nn;
    if (i == 0) *out_commit = g_commit / (float)((size_t)NROWS * DDIM);
}

// ---------------- launch ----------------
extern "C" void kernel_launch(void* const* d_in, const int* in_sizes, int n_in,
                              void* d_out, int out_size) {
    const float* ze = (const float*)d_in[0];
    const float* W  = (const float*)d_in[1];
    const float* mt = (const float*)d_in[2];
    const float* Nt = (const float*)d_in[3];
    float* out = (float*)d_out;

    const size_t off_zq     = 0;
    const size_t off_commit = (size_t)NROWS * DDIM;
    const size_t off_idx    = off_commit + 1;
    const size_t off_W      = off_idx + NROWS;
    const size_t off_mt     = off_W + (size_t)KCODES * DDIM;
    const size_t off_Nt     = off_mt + (size_t)KCODES * DDIM;

    k_prep<<<(NROWS * DDIM) / 256, 256>>>(ze, W);
    k_init<<<(KCODES * DDIM) / 256, 256>>>(W, mt, out + off_mt);

    dim3 grid(NROWS / 128, KCODES / 128);   // x = rowtile (fast) -> B coltile L2-hot
    k_gemm1<<<grid, 256>>>();

    k_phase2<<<NROWS / 8, 256>>>(ze, W);
    k_scatter<<<NROWS / 4, 256>>>(ze, W, out + off_zq, out + off_idx, out + off_mt);
    k_fin_nt<<<KCODES / 256, 256>>>(Nt, out + off_Nt);
    k_fin_w<<<(KCODES * DDIM) / 256, 256>>>(out + off_Nt, out + off_mt,
                                            out + off_W, out + off_commit);
}